// round 16
// baseline (speedup 1.0000x reference)
#include <cuda_runtime.h>
#include <cuda_fp16.h>
#include <math.h>

#define NB 16
#define NV 256
#define NR 1024
#define RMASK 1023
#define CS 1056          // table position stride (1024 + wrap extension), even

// OS-CFAR intermediate: half2 packs two adjacent v-rows; values pre-scaled by alpha/16. 8.4 MB.
__device__ __half2 g_os2[(NB * NV / 2) * NR];

#define CAS2(a, b) do { __half2 _hi = __hmax2(a, b); __half2 _lo = __hmin2(a, b); (a) = _hi; (b) = _lo; } while (0)

__device__ __forceinline__ __half2 u2h(unsigned u) { return *(__half2*)&u; }
__device__ __forceinline__ unsigned h2u(__half2 h) { return *(unsigned*)&h; }

// Batcher odd-even mergesort, 8 elems, descending (19 comparators).
__device__ __forceinline__ void sort8h(__half2* x) {
    CAS2(x[0], x[1]); CAS2(x[2], x[3]); CAS2(x[0], x[2]); CAS2(x[1], x[3]); CAS2(x[1], x[2]);
    CAS2(x[4], x[5]); CAS2(x[6], x[7]); CAS2(x[4], x[6]); CAS2(x[5], x[7]); CAS2(x[5], x[6]);
    CAS2(x[0], x[4]); CAS2(x[2], x[6]); CAS2(x[2], x[4]);
    CAS2(x[1], x[5]); CAS2(x[3], x[7]); CAS2(x[3], x[5]);
    CAS2(x[1], x[2]); CAS2(x[3], x[4]); CAS2(x[5], x[6]);
}

// M = sorted-desc top-8 of (sorted a) U (sorted b): half-cleaner + bitonic sort-8.
__device__ __forceinline__ void merge_top8(const __half2* a, const __half2* b, __half2* m) {
    m[0] = __hmax2(a[0], b[7]); m[1] = __hmax2(a[1], b[6]);
    m[2] = __hmax2(a[2], b[5]); m[3] = __hmax2(a[3], b[4]);
    m[4] = __hmax2(a[4], b[3]); m[5] = __hmax2(a[5], b[2]);
    m[6] = __hmax2(a[6], b[1]); m[7] = __hmax2(a[7], b[0]);
    CAS2(m[0], m[4]); CAS2(m[1], m[5]); CAS2(m[2], m[6]); CAS2(m[3], m[7]);
    CAS2(m[0], m[2]); CAS2(m[1], m[3]); CAS2(m[4], m[6]); CAS2(m[5], m[7]);
    CAS2(m[0], m[1]); CAS2(m[2], m[3]); CAS2(m[4], m[5]); CAS2(m[6], m[7]);
}

// 8th largest of union of two sorted-desc-8 lists = min_i max(A[i], B[7-i]).
__device__ __forceinline__ __half2 kth8(const __half2* a, const __half2* b) {
    __half2 m0 = __hmin2(__hmax2(a[0], b[7]), __hmax2(a[1], b[6]));
    __half2 m1 = __hmin2(__hmax2(a[2], b[5]), __hmax2(a[3], b[4]));
    __half2 m2 = __hmin2(__hmax2(a[4], b[3]), __hmax2(a[5], b[2]));
    __half2 m3 = __hmin2(__hmax2(a[6], b[1]), __hmax2(a[7], b[0]));
    return __hmin2(__hmin2(m0, m1), __hmin2(m2, m3));
}

// OS kernel v5 (best measured config): uint4-packed exchange tables, 2 blocks/SM.
// Thread t owns positions p = 2t, 2t+1; emits r = 2t+20, 2t+21.
__global__ void __launch_bounds__(512, 2) os5_kernel(const float* __restrict__ data, float ae) {
    extern __shared__ unsigned char sm[];
    __half2* row2 = (__half2*)sm;                         // 1040 half2 = 4160 B
    __half2* Lt   = (__half2*)(sm + 4160);                // 4*CS*2 half2 = 33792 B
    __half2* Mt   = (__half2*)(sm + 4160 + 33792);        // 33792 B

    const int t = threadIdx.x;
    const float2* srcA = (const float2*)(data + (size_t)(2 * blockIdx.x) * NR);
    const float2* srcB = (const float2*)(data + (size_t)(2 * blockIdx.x + 1) * NR);

    {   // load + scale + pack
        float2 fa = srcA[t], fb = srcB[t];
        __half2 h0 = __floats2half2_rn(fa.x * ae, fb.x * ae);
        __half2 h1 = __floats2half2_rn(fa.y * ae, fb.y * ae);
        row2[2 * t]     = h0;
        row2[2 * t + 1] = h1;
        if (t < 8) { row2[1024 + 2 * t] = h0; row2[1024 + 2 * t + 1] = h1; }
    }
    __syncthreads();

    // Phase A: sort L(2t), L(2t+1) in registers; publish packed.
    __half2 r[10];
    {
        const uint2* rp = (const uint2*)(row2 + 2 * t);
#pragma unroll
        for (int k = 0; k < 5; k++) {
            uint2 q = rp[k];
            r[2 * k]     = u2h(q.x);
            r[2 * k + 1] = u2h(q.y);
        }
    }
    __half2 La[8], Lb[8];
#pragma unroll
    for (int i = 0; i < 8; i++) { La[i] = r[i]; Lb[i] = r[i + 1]; }
    sort8h(La);
    sort8h(Lb);
#pragma unroll
    for (int c2 = 0; c2 < 4; c2++) {
        uint4 w;
        w.x = h2u(La[2 * c2]); w.y = h2u(La[2 * c2 + 1]);
        w.z = h2u(Lb[2 * c2]); w.w = h2u(Lb[2 * c2 + 1]);
        *(uint4*)(Lt + (c2 * CS + 2 * t) * 2) = w;
        if (t < 4) *(uint4*)(Lt + (c2 * CS + 2 * t + 1024) * 2) = w;   // wrap dup p<8
    }
    __syncthreads();

    // Phase B: M(p) = merge(L(p) [regs], L(p+8) [one LDS.128 per c-pair]).
    __half2 xb[8], yb[8];
#pragma unroll
    for (int c2 = 0; c2 < 4; c2++) {
        uint4 q = *(const uint4*)(Lt + (c2 * CS + 2 * t + 8) * 2);
        xb[2 * c2] = u2h(q.x); xb[2 * c2 + 1] = u2h(q.y);
        yb[2 * c2] = u2h(q.z); yb[2 * c2 + 1] = u2h(q.w);
    }
    __half2 M0[8], M1[8];
    merge_top8(La, xb, M0);
    merge_top8(Lb, yb, M1);
#pragma unroll
    for (int c2 = 0; c2 < 4; c2++) {
        uint4 w;
        w.x = h2u(M0[2 * c2]); w.y = h2u(M0[2 * c2 + 1]);
        w.z = h2u(M1[2 * c2]); w.w = h2u(M1[2 * c2 + 1]);
        *(uint4*)(Mt + (c2 * CS + 2 * t) * 2) = w;
        if (t < 13) *(uint4*)(Mt + (c2 * CS + 2 * t + 1024) * 2) = w;  // wrap dup p<26
    }
    __syncthreads();

    // Phase C: n0 = M(2t+25), n1 = M(2t+26) via LDS.64 pairs.
    __half2 n0[8], n1[8];
#pragma unroll
    for (int c2 = 0; c2 < 4; c2++) {
        uint2 qa = *(const uint2*)(Mt + (c2 * CS + 2 * t + 25) * 2);
        n0[2 * c2] = u2h(qa.x); n0[2 * c2 + 1] = u2h(qa.y);
        uint2 qb = *(const uint2*)(Mt + (c2 * CS + 2 * t + 26) * 2);
        n1[2 * c2] = u2h(qb.x); n1[2 * c2 + 1] = u2h(qb.y);
    }

    __half2 os0 = kth8(M0, n0);
    __half2 os1 = kth8(M1, n1);

    __half2* g2 = g_os2 + (size_t)blockIdx.x * NR;
    const int rr = (2 * t + 20) & RMASK;   // even; rr+1 adjacent
    uint2 o; o.x = h2u(os0); o.y = h2u(os1);
    *(uint2*)&g2[rr] = o;
}

// CA kernel (best measured form + wide loader): out(v) = box21(v) - box5(v);
// alpha/16 pre-folded. Block = (batch, 32-wide r chunk); tile unpacked fp32 in smem.
// Loader uses uint2 (r-pair) global loads + float2 smem stores: half the load-phase
// instructions of the scalar form; coalesced and bank-conflict-free.
__global__ void __launch_bounds__(512) ca_kernel(float* __restrict__ out) {
    __shared__ float tile[NV][32];
    const int b  = blockIdx.x >> 5;
    const int r0 = (blockIdx.x & 31) * 32;
    const int t  = threadIdx.x;

    const __half2* src = g_os2 + (size_t)b * (NV / 2) * NR + r0;
#pragma unroll
    for (int i = 0; i < 4; i++) {
        int idx = t + 512 * i;             // 0..2047 -> 128 vp x 16 r-pairs
        int vp = idx >> 4, rlp = idx & 15; // r-pair covers rl = 2*rlp, 2*rlp+1
        uint2 q = *(const uint2*)(src + (size_t)vp * NR + 2 * rlp);
        __half2 h0 = u2h(q.x);             // (vA, vB) @ rl
        __half2 h1 = u2h(q.y);             // (vA, vB) @ rl+1
        *(float2*)&tile[2 * vp][2 * rlp] =
            make_float2(__low2float(h0), __low2float(h1));
        *(float2*)&tile[2 * vp + 1][2 * rlp] =
            make_float2(__high2float(h0), __high2float(h1));
    }
    __syncthreads();

    const int rl = t & 31;
    const int v0 = (t >> 5) * 16;

    float box21 = 0.0f, box5 = 0.0f;
#pragma unroll
    for (int d = -10; d <= 10; d++) {
        float x = tile[(v0 + d) & (NV - 1)][rl];
        box21 += x;
        if (d >= -2 && d <= 2) box5 += x;
    }

    float* dst = out + (size_t)b * NV * NR + r0 + rl;
#pragma unroll
    for (int vi = 0; vi < 16; vi++) {
        const int v = v0 + vi;
        dst[(size_t)v * NR] = box21 - box5;
        box21 += tile[(v + 11) & (NV - 1)][rl] - tile[(v - 10) & (NV - 1)][rl];
        box5  += tile[(v + 3)  & (NV - 1)][rl] - tile[(v - 2)  & (NV - 1)][rl];
    }
}

// ---------------- host: replicate the reference's alpha solve ----------------

static double cfar_log_factorial(double n) {
    n += 1.0;
    if (n < 9.0) {
        double f = 1.0;
        int m = (int)(n + 0.5);
        for (int i = 2; i <= m; i++) f *= (double)i;
        return log(f);
    }
    return 0.5 * (log(2.0 * 3.14159265358979323846) - log(n))
         + n * (log(n + 1.0 / (12.0 * n - 1.0 / (10.0 * n))) - 1.0);
}

static double cfar_fun(int k, int n, double t, double pfa) {
    double s = 0.0;
    for (int j = n; j > n - k; j--) s += log((double)j + t);
    return cfar_log_factorial((double)n) - cfar_log_factorial((double)(n - k)) - s - log(pfa);
}

extern "C" void kernel_launch(void* const* d_in, const int* in_sizes, int n_in,
                              void* d_out, int out_size) {
    (void)in_sizes; (void)n_in; (void)out_size;
    const float* data = (const float*)d_in[0];
    float* out = (float*)d_out;

    double lo = 1.0, hi = 1.0e6;
    for (int it = 0; it < 200; it++) {
        double mid = 0.5 * (lo + hi);
        if (cfar_fun(24, 32, mid, 1.0e-5) > 0.0) lo = mid; else hi = mid;
    }
    float alpha_eff = (float)(sqrt(0.5 * (lo + hi)) / 16.0);   // alpha/16, CA divisor folded

    const int OS_SMEM = 4160 + 2 * 33792;          // 71744 B
    cudaFuncSetAttribute(os5_kernel, cudaFuncAttributeMaxDynamicSharedMemorySize, OS_SMEM);

    os5_kernel<<<NB * NV / 2, 512, OS_SMEM>>>(data, alpha_eff);
    ca_kernel<<<NB * 32, 512>>>(out);
}